// round 2
// baseline (speedup 1.0000x reference)
#include <cuda_runtime.h>

// ---------------------------------------------------------------------------
// Problem constants
// ---------------------------------------------------------------------------
#define BATCH   8
#define LSEQ    1024
#define DMODEL  1024
#define DINNER  4096
#define NHEAD   16
#define DK      64
#define MTOT    (BATCH * LSEQ)     // 8192 rows
#define MAXREL  16
#define NREL    (2 * MAXREL + 1)   // 33

// ---------------------------------------------------------------------------
// Scratch (static device globals; no allocation allowed)
// ---------------------------------------------------------------------------
__device__ float g_Q  [(size_t)MTOT * DMODEL];
__device__ float g_K  [(size_t)MTOT * DMODEL];
__device__ float g_V  [(size_t)MTOT * DMODEL];
__device__ float g_att[(size_t)MTOT * DMODEL];
__device__ float g_fc [(size_t)MTOT * DMODEL];
__device__ float g_ln1[(size_t)MTOT * DMODEL];
__device__ float g_h1 [(size_t)MTOT * DINNER];
__device__ float g_h2 [(size_t)MTOT * DMODEL];

// ---------------------------------------------------------------------------
// f32x2 packed-math helpers (Blackwell doubles fp32 throughput via f32x2)
// ---------------------------------------------------------------------------
__device__ __forceinline__ unsigned long long pack2(float lo, float hi) {
    unsigned long long r;
    asm("mov.b64 %0, {%1, %2};" : "=l"(r) : "f"(lo), "f"(hi));
    return r;
}
__device__ __forceinline__ void unpack2(float& lo, float& hi, unsigned long long v) {
    asm("mov.b64 {%0, %1}, %2;" : "=f"(lo), "=f"(hi) : "l"(v));
}
__device__ __forceinline__ void ffma2(unsigned long long& d,
                                      unsigned long long a,
                                      unsigned long long b) {
    asm("fma.rn.f32x2 %0, %1, %2, %0;" : "+l"(d) : "l"(a), "l"(b));
}

// ---------------------------------------------------------------------------
// Core SGEMM tile routine: 128x128 block tile, BK=8, 256 threads,
// 8x8 microtile, f32x2 inner product, double-buffered shared memory
// (register prefetch of the next K-slice overlapped with compute).
// ---------------------------------------------------------------------------
template <int RELU>
__device__ __forceinline__ void sgemm_tile(const float* __restrict__ A,
                                           const float* __restrict__ W,
                                           const float* __restrict__ bias,
                                           float* __restrict__ C,
                                           int N, int K, int bm, int bn)
{
    __shared__ float As[2][8][132];   // padded: conflict-free transposed stores
    __shared__ float Bs[2][8][128];

    const int tid = threadIdx.x;
    const int tx  = tid & 15;      // 16 thread cols * 8 = 128
    const int ty  = tid >> 4;      // 16 thread rows * 8 = 128

    // global-load assignments
    const int a_row = tid >> 1;            // 128 rows, 2 threads/row
    const int a_col = (tid & 1) * 4;       // 0 or 4
    const int b_row = tid >> 5;            // 8 rows
    const int b_col = (tid & 31) * 4;      // 128 cols / float4

    const float* Ap = A + (size_t)(bm + a_row) * K + a_col;
    const float* Wp = W + (size_t)b_row * N + bn + b_col;

    unsigned long long acc[8][4];
#pragma unroll
    for (int i = 0; i < 8; i++)
#pragma unroll
        for (int j = 0; j < 4; j++) acc[i][j] = 0ULL;

    // prologue: load tile 0 into buffer 0
    {
        float4 av = *(const float4*)Ap;  Ap += 8;
        float4 bv = *(const float4*)Wp;  Wp += (size_t)8 * N;
        As[0][a_col + 0][a_row] = av.x;
        As[0][a_col + 1][a_row] = av.y;
        As[0][a_col + 2][a_row] = av.z;
        As[0][a_col + 3][a_row] = av.w;
        *(float4*)&Bs[0][b_row][b_col] = bv;
    }
    __syncthreads();

    int cur = 0;
    for (int k0 = 0; k0 < K; k0 += 8) {
        const bool has_next = (k0 + 8) < K;
        float4 av, bv;
        if (has_next) {                    // prefetch next slice (GMEM -> regs)
            av = *(const float4*)Ap;  Ap += 8;
            bv = *(const float4*)Wp;  Wp += (size_t)8 * N;
        }

#pragma unroll
        for (int kk = 0; kk < 8; kk++) {
            float a[8];
            *(float4*)(a)     = *(const float4*)&As[cur][kk][ty * 8];
            *(float4*)(a + 4) = *(const float4*)&As[cur][kk][ty * 8 + 4];
            float4 b0 = *(const float4*)&Bs[cur][kk][tx * 8];
            float4 b1 = *(const float4*)&Bs[cur][kk][tx * 8 + 4];
            unsigned long long bp[4];
            bp[0] = pack2(b0.x, b0.y);
            bp[1] = pack2(b0.z, b0.w);
            bp[2] = pack2(b1.x, b1.y);
            bp[3] = pack2(b1.z, b1.w);
#pragma unroll
            for (int i = 0; i < 8; i++) {
                unsigned long long ap = pack2(a[i], a[i]);
#pragma unroll
                for (int j = 0; j < 4; j++) ffma2(acc[i][j], ap, bp[j]);
            }
        }

        if (has_next) {                    // regs -> alternate smem buffer
            const int nxt = cur ^ 1;
            As[nxt][a_col + 0][a_row] = av.x;
            As[nxt][a_col + 1][a_row] = av.y;
            As[nxt][a_col + 2][a_row] = av.z;
            As[nxt][a_col + 3][a_row] = av.w;
            *(float4*)&Bs[nxt][b_row][b_col] = bv;
            __syncthreads();
            cur = nxt;
        }
    }

    // epilogue
    const int row0 = bm + ty * 8;
    const int col0 = bn + tx * 8;
    float bb[8];
    *(float4*)(bb)     = *(const float4*)(bias + col0);
    *(float4*)(bb + 4) = *(const float4*)(bias + col0 + 4);

#pragma unroll
    for (int i = 0; i < 8; i++) {
        float c[8];
#pragma unroll
        for (int j = 0; j < 4; j++) {
            float lo, hi;
            unpack2(lo, hi, acc[i][j]);
            c[2 * j]     = lo + bb[2 * j];
            c[2 * j + 1] = hi + bb[2 * j + 1];
        }
        if (RELU) {
#pragma unroll
            for (int j = 0; j < 8; j++) c[j] = fmaxf(c[j], 0.0f);
        }
        float* crow = C + (size_t)(row0 + i) * N + col0;
        *(float4*)(crow)     = *(const float4*)(c);
        *(float4*)(crow + 4) = *(const float4*)(c + 4);
    }
}

// Generic single-GEMM kernel
template <int RELU>
__global__ void __launch_bounds__(256)
sgemm_kernel(const float* __restrict__ A,
             const float* __restrict__ W,
             const float* __restrict__ bias,
             float* __restrict__ C,
             int M, int N, int K)
{
    sgemm_tile<RELU>(A, W, bias, C, N, K, blockIdx.y * 128, blockIdx.x * 128);
}

// Fused Q/K/V projection: blockIdx.z selects which of the three GEMMs.
// All three share shapes [MTOT,1024] @ [1024,1024]; one launch = one tail wave.
__global__ void __launch_bounds__(256)
qkv_gemm_kernel(const float* __restrict__ q, const float* __restrict__ k,
                const float* __restrict__ v,
                const float* __restrict__ wq, const float* __restrict__ wk,
                const float* __restrict__ wv,
                const float* __restrict__ bq, const float* __restrict__ bk,
                const float* __restrict__ bv,
                float* __restrict__ oq, float* __restrict__ ok,
                float* __restrict__ ov)
{
    const int z = blockIdx.z;
    const float* A    = (z == 0) ? q  : (z == 1) ? k  : v;
    const float* W    = (z == 0) ? wq : (z == 1) ? wk : wv;
    const float* bias = (z == 0) ? bq : (z == 1) ? bk : bv;
    float*       C    = (z == 0) ? oq : (z == 1) ? ok : ov;
    sgemm_tile<0>(A, W, bias, C, DMODEL, DMODEL, blockIdx.y * 128, blockIdx.x * 128);
}

// ---------------------------------------------------------------------------
// Fused relative-position attention (flash style, fp32).
// One thread per query. Grid: (L/128, NHEAD, BATCH); 128 threads/block.
// Shaw bias folded in via 33 precomputed dots (Qrel); weight2 via 33 buckets.
// ---------------------------------------------------------------------------
#define BKV 64
#define ATTN_SMEM_FLOATS (BKV*DK /*Kt*/ + BKV*DK /*Vt*/ + 128*NREL /*Qrel*/ \
                          + 128*NREL /*Bkt*/ + NREL*DK /*RelV*/)
#define ATTN_SMEM_BYTES  (ATTN_SMEM_FLOATS * 4)

__global__ void __launch_bounds__(128)
attn_kernel(const float* __restrict__ Q,
            const float* __restrict__ K,
            const float* __restrict__ V,
            const float* __restrict__ rel_k,
            const float* __restrict__ rel_v,
            float* __restrict__ O)
{
    extern __shared__ float sm[];
    float* Kt   = sm;                        // [BKV][64]
    float* Vt   = Kt + BKV * DK;             // [BKV][64]
    float* Qrel = Vt + BKV * DK;             // [128][33]
    float* Bkt  = Qrel + 128 * NREL;         // [128][33]
    float* RelV = Bkt + 128 * NREL;          // [33][64]

    const int tid = threadIdx.x;
    const int b   = blockIdx.z;
    const int h   = blockIdx.y;
    const int q   = blockIdx.x * 128 + tid;

    // cooperative load of rel_v into smem (33*64 = 2112 floats = 528 float4)
    for (int i = tid; i < NREL * DK / 4; i += 128)
        ((float4*)RelV)[i] = ((const float4*)rel_v)[i];

    // load this thread's query vector (64 floats)
    const float* Qrow = Q + ((size_t)b * LSEQ + q) * DMODEL + h * DK;
    float4 q4[16];
#pragma unroll
    for (int i = 0; i < 16; i++) q4[i] = ((const float4*)Qrow)[i];

    // Qrel[r] = Qh . rel_k[r]; also zero buckets
#pragma unroll 1
    for (int r = 0; r < NREL; r++) {
        const float4* rk = (const float4*)(rel_k + r * DK);
        float s = 0.f;
#pragma unroll
        for (int i = 0; i < 16; i++) {
            float4 kv = __ldg(rk + i);
            s += q4[i].x * kv.x + q4[i].y * kv.y + q4[i].z * kv.z + q4[i].w * kv.w;
        }
        Qrel[tid * NREL + r] = s;
        Bkt[tid * NREL + r]  = 0.f;
    }

    float m = -1e30f, l = 0.f;
    float4 acc[16];
#pragma unroll
    for (int i = 0; i < 16; i++) acc[i] = make_float4(0.f, 0.f, 0.f, 0.f);

    const float* Kbase = K + (size_t)b * LSEQ * DMODEL + h * DK;
    const float* Vbase = V + (size_t)b * LSEQ * DMODEL + h * DK;

    for (int k0 = 0; k0 < LSEQ; k0 += BKV) {
        __syncthreads();
        // load K/V tile: BKV*64 floats = BKV*16 float4 each
        for (int i = tid; i < BKV * 16; i += 128) {
            int r = i >> 4, c = i & 15;
            ((float4*)Kt)[i] = __ldg((const float4*)(Kbase + (size_t)(k0 + r) * DMODEL) + c);
            ((float4*)Vt)[i] = __ldg((const float4*)(Vbase + (size_t)(k0 + r) * DMODEL) + c);
        }
        __syncthreads();

#pragma unroll 1
        for (int kk = 0; kk < BKV; kk++) {
            const float4* kr = (const float4*)(Kt + kk * DK);
            float s = 0.f;
#pragma unroll
            for (int i = 0; i < 16; i++) {
                float4 kv = kr[i];
                s += q4[i].x * kv.x + q4[i].y * kv.y + q4[i].z * kv.z + q4[i].w * kv.w;
            }
            int d   = (k0 + kk) - q;
            int idx = min(max(d, -MAXREL), MAXREL) + MAXREL;
            s = 0.125f * (s + Qrel[tid * NREL + idx]);   // 1/sqrt(64)

            if (s > m) {
                float f = __expf(m - s);
                m = s;
                l *= f;
#pragma unroll
                for (int i = 0; i < 16; i++) {
                    acc[i].x *= f; acc[i].y *= f; acc[i].z *= f; acc[i].w *= f;
                }
#pragma unroll
                for (int r = 0; r < NREL; r++) Bkt[tid * NREL + r] *= f;
            }
            float e = __expf(s - m);
            l += e;
            Bkt[tid * NREL + idx] += e;

            const float4* vr = (const float4*)(Vt + kk * DK);
#pragma unroll
            for (int i = 0; i < 16; i++) {
                float4 vv = vr[i];
                acc[i].x += e * vv.x; acc[i].y += e * vv.y;
                acc[i].z += e * vv.z; acc[i].w += e * vv.w;
            }
        }
    }

    // epilogue: weight2 from buckets, normalize, store in [B, L, H*DV] layout
#pragma unroll 1
    for (int r = 0; r < NREL; r++) {
        float p = Bkt[tid * NREL + r];
        const float4* rv = (const float4*)(RelV + r * DK);
#pragma unroll
        for (int i = 0; i < 16; i++) {
            float4 t = rv[i];
            acc[i].x += p * t.x; acc[i].y += p * t.y;
            acc[i].z += p * t.z; acc[i].w += p * t.w;
        }
    }
    float inv = 1.f / l;
    float4* orow = (float4*)(O + ((size_t)b * LSEQ + q) * DMODEL + h * DK);
#pragma unroll
    for (int i = 0; i < 16; i++) {
        float4 o;
        o.x = acc[i].x * inv; o.y = acc[i].y * inv;
        o.z = acc[i].z * inv; o.w = acc[i].w * inv;
        orow[i] = o;
    }
}

// ---------------------------------------------------------------------------
// Fused residual-add + LayerNorm. One block (256 thr) per 1024-elem row.
// ---------------------------------------------------------------------------
__device__ __forceinline__ float warpsum(float v) {
#pragma unroll
    for (int o = 16; o; o >>= 1) v += __shfl_xor_sync(0xffffffffu, v, o);
    return v;
}

__global__ void __launch_bounds__(256)
ln_kernel(const float* __restrict__ x, const float* __restrict__ res,
          const float* __restrict__ g, const float* __restrict__ bta,
          float* __restrict__ out)
{
    const int row = blockIdx.x;
    const int t   = threadIdx.x;
    const float4* xr = (const float4*)(x   + (size_t)row * DMODEL);
    const float4* rr = (const float4*)(res + (size_t)row * DMODEL);

    float4 v = xr[t], r4 = rr[t];
    v.x += r4.x; v.y += r4.y; v.z += r4.z; v.w += r4.w;
    float s  = v.x + v.y + v.z + v.w;
    float ss = v.x * v.x + v.y * v.y + v.z * v.z + v.w * v.w;

    s  = warpsum(s);
    ss = warpsum(ss);

    __shared__ float aS[8], aQ[8];
    __shared__ float mu_s, rs_s;
    const int w = t >> 5, ln = t & 31;
    if (ln == 0) { aS[w] = s; aQ[w] = ss; }
    __syncthreads();
    if (t == 0) {
        float S = 0.f, Q2 = 0.f;
#pragma unroll
        for (int i = 0; i < 8; i++) { S += aS[i]; Q2 += aQ[i]; }
        float mu  = S * (1.f / DMODEL);
        float var = Q2 * (1.f / DMODEL) - mu * mu;
        mu_s = mu;
        rs_s = rsqrtf(var + 1e-6f);
    }
    __syncthreads();
    const float mu = mu_s, rs = rs_s;

    float4 gg = ((const float4*)g)[t];
    float4 bb = ((const float4*)bta)[t];
    float4 o;
    o.x = (v.x - mu) * rs * gg.x + bb.x;
    o.y = (v.y - mu) * rs * gg.y + bb.y;
    o.z = (v.z - mu) * rs * gg.z + bb.z;
    o.w = (v.w - mu) * rs * gg.w + bb.w;
    ((float4*)(out + (size_t)row * DMODEL))[t] = o;
}

// ---------------------------------------------------------------------------
// Launch sequence
// ---------------------------------------------------------------------------
extern "C" void kernel_launch(void* const* d_in, const int* in_sizes, int n_in,
                              void* d_out, int out_size)
{
    const float* q_in  = (const float*)d_in[0];
    const float* k_in  = (const float*)d_in[1];
    const float* v_in  = (const float*)d_in[2];
    const float* wq    = (const float*)d_in[3];
    const float* bq    = (const float*)d_in[4];
    const float* wk    = (const float*)d_in[5];
    const float* bk    = (const float*)d_in[6];
    const float* wv    = (const float*)d_in[7];
    const float* bv    = (const float*)d_in[8];
    const float* wfc   = (const float*)d_in[9];
    const float* bfc   = (const float*)d_in[10];
    const float* w1    = (const float*)d_in[11];
    const float* b1    = (const float*)d_in[12];
    const float* w2    = (const float*)d_in[13];
    const float* b2    = (const float*)d_in[14];
    const float* ln_g  = (const float*)d_in[15];
    const float* ln_b  = (const float*)d_in[16];
    const float* rel_k = (const float*)d_in[17];
    const float* rel_v = (const float*)d_in[18];
    float* out = (float*)d_out;

    float *pQ, *pK, *pV, *pAtt, *pFc, *pLn1, *pH1, *pH2;
    cudaGetSymbolAddress((void**)&pQ,   g_Q);
    cudaGetSymbolAddress((void**)&pK,   g_K);
    cudaGetSymbolAddress((void**)&pV,   g_V);
    cudaGetSymbolAddress((void**)&pAtt, g_att);
    cudaGetSymbolAddress((void**)&pFc,  g_fc);
    cudaGetSymbolAddress((void**)&pLn1, g_ln1);
    cudaGetSymbolAddress((void**)&pH1,  g_h1);
    cudaGetSymbolAddress((void**)&pH2,  g_h2);

    cudaFuncSetAttribute(attn_kernel,
                         cudaFuncAttributeMaxDynamicSharedMemorySize,
                         ATTN_SMEM_BYTES);

    dim3 blk(256);
    dim3 g_qkv (DMODEL / 128, MTOT / 128, 3);  // fused Q/K/V projections
    dim3 g_1024(DMODEL / 128, MTOT / 128);     // N=1024 gemms
    dim3 g_4096(DINNER / 128, MTOT / 128);     // N=4096 gemm

    // Q/K/V projections (one launch, z selects GEMM)
    qkv_gemm_kernel<<<g_qkv, blk>>>(q_in, k_in, v_in, wq, wk, wv,
                                    bq, bk, bv, pQ, pK, pV);

    // fused relative attention
    dim3 agrid(LSEQ / 128, NHEAD, BATCH);
    attn_kernel<<<agrid, 128, ATTN_SMEM_BYTES>>>(pQ, pK, pV, rel_k, rel_v, pAtt);

    // output projection + residual + LN
    sgemm_kernel<0><<<g_1024, blk>>>(pAtt, wfc, bfc, pFc, MTOT, DMODEL, DMODEL);
    ln_kernel<<<MTOT, 256>>>(pFc, q_in, ln_g, ln_b, pLn1);

    // FFN + residual + LN
    sgemm_kernel<1><<<g_4096, blk>>>(pLn1, w1, b1, pH1, MTOT, DINNER, DMODEL);
    sgemm_kernel<0><<<g_1024, blk>>>(pH1, w2, b2, pH2, MTOT, DMODEL, DINNER);
    ln_kernel<<<MTOT, 256>>>(pH2, pLn1, ln_g, ln_b, out);
}

// round 11
// speedup vs baseline: 2.0739x; 2.0739x over previous
#include <cuda_runtime.h>
#include <cstdint>

// ---------------------------------------------------------------------------
// Problem constants
// ---------------------------------------------------------------------------
#define BATCH   8
#define LSEQ    1024
#define DMODEL  1024
#define DINNER  4096
#define NHEAD   16
#define DK      64
#define MTOT    (BATCH * LSEQ)     // 8192 rows
#define MAXREL  16
#define NREL    (2 * MAXREL + 1)   // 33

// ---------------------------------------------------------------------------
// Scratch (static device globals; no allocation allowed)
// ---------------------------------------------------------------------------
__device__ float g_Q  [(size_t)MTOT * DMODEL];
__device__ float g_K  [(size_t)MTOT * DMODEL];
__device__ float g_V  [(size_t)MTOT * DMODEL];
__device__ float g_att[(size_t)MTOT * DMODEL];
__device__ float g_fc [(size_t)MTOT * DMODEL];
__device__ float g_ln1[(size_t)MTOT * DMODEL];
__device__ float g_h1 [(size_t)MTOT * DINNER];
__device__ float g_h2 [(size_t)MTOT * DMODEL];
// tf32-rounded (rna) copies of GEMM operands
__device__ float g_rq [(size_t)MTOT * DMODEL];
__device__ float g_rk [(size_t)MTOT * DMODEL];
__device__ float g_rv [(size_t)MTOT * DMODEL];
__device__ float g_rwq[(size_t)DMODEL * DMODEL];
__device__ float g_rwk[(size_t)DMODEL * DMODEL];
__device__ float g_rwv[(size_t)DMODEL * DMODEL];
__device__ float g_rwf[(size_t)DMODEL * DMODEL];
__device__ float g_rw1[(size_t)DMODEL * DINNER];
__device__ float g_rw2[(size_t)DINNER * DMODEL];

// ---------------------------------------------------------------------------
// Helpers
// ---------------------------------------------------------------------------
__device__ __forceinline__ float tf32r(float x) {
    uint32_t u;
    asm("cvt.rna.tf32.f32 %0, %1;" : "=r"(u) : "f"(x));
    return __uint_as_float(u);
}

__device__ __forceinline__ void cp_async_cg(uint32_t saddr, const void* g) {
    asm volatile("cp.async.cg.shared.global [%0], [%1], 16;"
                 :: "r"(saddr), "l"(g));
}
__device__ __forceinline__ void cp_commit() {
    asm volatile("cp.async.commit_group;" ::: "memory");
}
__device__ __forceinline__ void cp_wait1() {
    asm volatile("cp.async.wait_group 1;" ::: "memory");
}
__device__ __forceinline__ void cp_wait0() {
    asm volatile("cp.async.wait_group 0;" ::: "memory");
}

__device__ __forceinline__ void ldsm_x4(uint32_t r[4], uint32_t saddr) {
    asm volatile("ldmatrix.sync.aligned.m8n8.x4.shared.b16 {%0,%1,%2,%3}, [%4];"
                 : "=r"(r[0]), "=r"(r[1]), "=r"(r[2]), "=r"(r[3])
                 : "r"(saddr) : "memory");
}

__device__ __forceinline__ void mma_tf32(float c[4], const uint32_t a[4],
                                         uint32_t b0, uint32_t b1) {
    asm volatile(
        "mma.sync.aligned.m16n8k8.row.col.f32.tf32.tf32.f32 "
        "{%0,%1,%2,%3},{%4,%5,%6,%7},{%8,%9},{%0,%1,%2,%3};"
        : "+f"(c[0]), "+f"(c[1]), "+f"(c[2]), "+f"(c[3])
        : "r"(a[0]), "r"(a[1]), "r"(a[2]), "r"(a[3]), "r"(b0), "r"(b1));
}

// ---------------------------------------------------------------------------
// tf32 tensor-core GEMM: C[M,N] = A[M,K] @ W[K,N] + bias, opt ReLU / tf32-round.
// 128x128 block tile, BK=32, 256 threads (8 warps, 2x4), warp tile 64x32.
// cp.async double-buffered smem; ldmatrix for A frags; padded strides for
// conflict-free access (A stride 36, B stride 136).
// ---------------------------------------------------------------------------
#define BM 128
#define BN 128
#define BK 32
#define AS_STRIDE 36
#define BS_STRIDE 136
#define AS_SIZE   (BM * AS_STRIDE)              // 4608 u32
#define BS_SIZE   (BK * BS_STRIDE)              // 4352 u32
#define GSMEM_BYTES ((AS_SIZE + BS_SIZE) * 2 * 4)  // 71680 B

template <int RELU, int RND>
__device__ __forceinline__ void mm_tile(const float* __restrict__ A,
                                        const float* __restrict__ W,
                                        const float* __restrict__ bias,
                                        float* __restrict__ C,
                                        int N, int K, int bm, int bn)
{
    extern __shared__ uint32_t gsm[];
    uint32_t* Bs = gsm + 2 * AS_SIZE;

    const int tid  = threadIdx.x;
    const int lane = tid & 31;
    const int warp = tid >> 5;
    const int wm = (warp >> 2) * 64;   // warp row offset (2 rows of warps)
    const int wn = (warp & 3) * 32;    // warp col offset (4 cols of warps)
    const int lr = lane >> 2;          // 0..7
    const int lc = lane & 3;           // 0..3

    const uint32_t sbase = (uint32_t)__cvta_generic_to_shared(gsm);

    // global->smem loader coords
    const int a_r0 = tid >> 3, a_cv = tid & 7;   // A: 128 rows x 8 float4
    const int b_k0 = tid >> 5, b_nv = tid & 31;  // B: 32 rows x 32 float4

    // ldmatrix per-lane addressing: 4 8x8(b16) matrices = m16k8 tf32 frag
    const int lm_row = (lane & 7) + ((lane >> 3) & 1) * 8;
    const int lm_c   = (lane >> 4) * 4;

    float acc[4][4][4];
#pragma unroll
    for (int i = 0; i < 4; i++)
#pragma unroll
        for (int j = 0; j < 4; j++)
#pragma unroll
            for (int k = 0; k < 4; k++) acc[i][j][k] = 0.f;

#define LOAD_TILE(buf, k0)                                                     \
    {                                                                          \
        _Pragma("unroll")                                                      \
        for (int i = 0; i < 4; i++) {                                          \
            int r = a_r0 + 32 * i;                                             \
            cp_async_cg(sbase + (uint32_t)(((buf) * AS_SIZE +                  \
                         r * AS_STRIDE + a_cv * 4) * 4),                       \
                        A + (size_t)(bm + r) * K + (k0) + a_cv * 4);           \
        }                                                                      \
        _Pragma("unroll")                                                      \
        for (int i = 0; i < 4; i++) {                                          \
            int kr = b_k0 + 8 * i;                                             \
            cp_async_cg(sbase + (uint32_t)((2 * AS_SIZE + (buf) * BS_SIZE +    \
                         kr * BS_STRIDE + b_nv * 4) * 4),                      \
                        W + (size_t)((k0) + kr) * N + bn + b_nv * 4);          \
        }                                                                      \
        cp_commit();                                                           \
    }

    LOAD_TILE(0, 0);
    const int T = K / BK;
    for (int t = 0; t < T; t++) {
        if (t + 1 < T) { LOAD_TILE((t + 1) & 1, (t + 1) * BK); cp_wait1(); }
        else           { cp_wait0(); }
        __syncthreads();

        const uint32_t a_sb = sbase + (uint32_t)(((t & 1) * AS_SIZE) * 4);
        const uint32_t* Bb  = Bs + (t & 1) * BS_SIZE;

#pragma unroll
        for (int kk = 0; kk < BK; kk += 8) {
            uint32_t a[4][4];
#pragma unroll
            for (int mi = 0; mi < 4; mi++) {
                uint32_t addr = a_sb +
                    (uint32_t)(((wm + mi * 16 + lm_row) * AS_STRIDE + kk + lm_c) * 4);
                ldsm_x4(a[mi], addr);
            }
            uint32_t b[4][2];
#pragma unroll
            for (int ni = 0; ni < 4; ni++) {
                const uint32_t* p = Bb + (kk + lc) * BS_STRIDE + wn + ni * 8 + lr;
                b[ni][0] = p[0];
                b[ni][1] = p[4 * BS_STRIDE];
            }
#pragma unroll
            for (int mi = 0; mi < 4; mi++)
#pragma unroll
                for (int ni = 0; ni < 4; ni++)
                    mma_tf32(acc[mi][ni], a[mi], b[ni][0], b[ni][1]);
        }
        __syncthreads();
    }
#undef LOAD_TILE

    // epilogue: bias (+ReLU) (+tf32 rna rounding), fragment layout stores
#pragma unroll
    for (int mi = 0; mi < 4; mi++) {
        const int row = bm + wm + mi * 16 + lr;
#pragma unroll
        for (int ni = 0; ni < 4; ni++) {
            const int col = bn + wn + ni * 8 + 2 * lc;
            const float b0 = bias[col], b1 = bias[col + 1];
            float v0 = acc[mi][ni][0] + b0;
            float v1 = acc[mi][ni][1] + b1;
            float v2 = acc[mi][ni][2] + b0;
            float v3 = acc[mi][ni][3] + b1;
            if (RELU) {
                v0 = fmaxf(v0, 0.f); v1 = fmaxf(v1, 0.f);
                v2 = fmaxf(v2, 0.f); v3 = fmaxf(v3, 0.f);
            }
            if (RND) {
                v0 = tf32r(v0); v1 = tf32r(v1);
                v2 = tf32r(v2); v3 = tf32r(v3);
            }
            float2 lo = make_float2(v0, v1);
            float2 hi = make_float2(v2, v3);
            *(float2*)(C + (size_t)row * N + col)       = lo;
            *(float2*)(C + (size_t)(row + 8) * N + col) = hi;
        }
    }
}

template <int RELU, int RND>
__global__ void __launch_bounds__(256)
mm_kernel(const float* __restrict__ A, const float* __restrict__ W,
          const float* __restrict__ bias, float* __restrict__ C,
          int N, int K)
{
    mm_tile<RELU, RND>(A, W, bias, C, N, K, blockIdx.y * BM, blockIdx.x * BN);
}

// Fused Q/K/V projection: blockIdx.z selects the GEMM (one launch, one tail).
__global__ void __launch_bounds__(256)
qkv_mm_kernel(const float* __restrict__ q, const float* __restrict__ k,
              const float* __restrict__ v,
              const float* __restrict__ wq, const float* __restrict__ wk,
              const float* __restrict__ wv,
              const float* __restrict__ bq, const float* __restrict__ bk,
              const float* __restrict__ bv,
              float* __restrict__ oq, float* __restrict__ ok,
              float* __restrict__ ov)
{
    const int z = blockIdx.z;
    const float* A    = (z == 0) ? q  : (z == 1) ? k  : v;
    const float* W    = (z == 0) ? wq : (z == 1) ? wk : wv;
    const float* bias = (z == 0) ? bq : (z == 1) ? bk : bv;
    float*       C    = (z == 0) ? oq : (z == 1) ? ok : ov;
    mm_tile<0, 0>(A, W, bias, C, DMODEL, DMODEL, blockIdx.y * BM, blockIdx.x * BN);
}

// ---------------------------------------------------------------------------
// Elementwise tf32-rna rounding pass (for external GEMM operands)
// ---------------------------------------------------------------------------
__global__ void __launch_bounds__(256)
round_kernel(const float* __restrict__ src, float* __restrict__ dst, int n4)
{
    int i = blockIdx.x * 256 + threadIdx.x;
    if (i < n4) {
        float4 v = ((const float4*)src)[i];
        v.x = tf32r(v.x); v.y = tf32r(v.y);
        v.z = tf32r(v.z); v.w = tf32r(v.w);
        ((float4*)dst)[i] = v;
    }
}

// ---------------------------------------------------------------------------
// Fused relative-position attention (flash style, fp32); output rna-rounded
// (it feeds the wfc GEMM).
// ---------------------------------------------------------------------------
#define BKV 64
#define ATTN_SMEM_FLOATS (BKV*DK + BKV*DK + 128*NREL + 128*NREL + NREL*DK)
#define ATTN_SMEM_BYTES  (ATTN_SMEM_FLOATS * 4)

__global__ void __launch_bounds__(128)
attn_kernel(const float* __restrict__ Q,
            const float* __restrict__ K,
            const float* __restrict__ V,
            const float* __restrict__ rel_k,
            const float* __restrict__ rel_v,
            float* __restrict__ O)
{
    extern __shared__ float sm[];
    float* Kt   = sm;                        // [BKV][64]
    float* Vt   = Kt + BKV * DK;             // [BKV][64]
    float* Qrel = Vt + BKV * DK;             // [128][33]
    float* Bkt  = Qrel + 128 * NREL;         // [128][33]
    float* RelV = Bkt + 128 * NREL;          // [33][64]

    const int tid = threadIdx.x;
    const int b   = blockIdx.z;
    const int h   = blockIdx.y;
    const int q   = blockIdx.x * 128 + tid;

    for (int i = tid; i < NREL * DK / 4; i += 128)
        ((float4*)RelV)[i] = ((const float4*)rel_v)[i];

    const float* Qrow = Q + ((size_t)b * LSEQ + q) * DMODEL + h * DK;
    float4 q4[16];
#pragma unroll
    for (int i = 0; i < 16; i++) q4[i] = ((const float4*)Qrow)[i];

#pragma unroll 1
    for (int r = 0; r < NREL; r++) {
        const float4* rk = (const float4*)(rel_k + r * DK);
        float s = 0.f;
#pragma unroll
        for (int i = 0; i < 16; i++) {
            float4 kv = __ldg(rk + i);
            s += q4[i].x * kv.x + q4[i].y * kv.y + q4[i].z * kv.z + q4[i].w * kv.w;
        }
        Qrel[tid * NREL + r] = s;
        Bkt[tid * NREL + r]  = 0.f;
    }

    float m = -1e30f, l = 0.f;
    float4 acc[16];
#pragma unroll
    for (int i = 0; i < 16; i++) acc[i] = make_float4(0.f, 0.f, 0.f, 0.f);

    const float* Kbase = K + (size_t)b * LSEQ * DMODEL + h * DK;
    const float* Vbase = V + (size_t)b * LSEQ * DMODEL + h * DK;

    for (int k0 = 0; k0 < LSEQ; k0 += BKV) {
        __syncthreads();
        for (int i = tid; i < BKV * 16; i += 128) {
            int r = i >> 4, c = i & 15;
            ((float4*)Kt)[i] = __ldg((const float4*)(Kbase + (size_t)(k0 + r) * DMODEL) + c);
            ((float4*)Vt)[i] = __ldg((const float4*)(Vbase + (size_t)(k0 + r) * DMODEL) + c);
        }
        __syncthreads();

#pragma unroll 1
        for (int kk = 0; kk < BKV; kk++) {
            const float4* kr = (const float4*)(Kt + kk * DK);
            float s = 0.f;
#pragma unroll
            for (int i = 0; i < 16; i++) {
                float4 kv = kr[i];
                s += q4[i].x * kv.x + q4[i].y * kv.y + q4[i].z * kv.z + q4[i].w * kv.w;
            }
            int d   = (k0 + kk) - q;
            int idx = min(max(d, -MAXREL), MAXREL) + MAXREL;
            s = 0.125f * (s + Qrel[tid * NREL + idx]);

            if (s > m) {
                float f = __expf(m - s);
                m = s;
                l *= f;
#pragma unroll
                for (int i = 0; i < 16; i++) {
                    acc[i].x *= f; acc[i].y *= f; acc[i].z *= f; acc[i].w *= f;
                }
#pragma unroll
                for (int r = 0; r < NREL; r++) Bkt[tid * NREL + r] *= f;
            }
            float e = __expf(s - m);
            l += e;
            Bkt[tid * NREL + idx] += e;

            const float4* vr = (const float4*)(Vt + kk * DK);
#pragma unroll
            for (int i = 0; i < 16; i++) {
                float4 vv = vr[i];
                acc[i].x += e * vv.x; acc[i].y += e * vv.y;
                acc[i].z += e * vv.z; acc[i].w += e * vv.w;
            }
        }
    }

#pragma unroll 1
    for (int r = 0; r < NREL; r++) {
        float p = Bkt[tid * NREL + r];
        const float4* rv = (const float4*)(RelV + r * DK);
#pragma unroll
        for (int i = 0; i < 16; i++) {
            float4 t = rv[i];
            acc[i].x += p * t.x; acc[i].y += p * t.y;
            acc[i].z += p * t.z; acc[i].w += p * t.w;
        }
    }
    float inv = 1.f / l;
    float4* orow = (float4*)(O + ((size_t)b * LSEQ + q) * DMODEL + h * DK);
#pragma unroll
    for (int i = 0; i < 16; i++) {
        float4 o;
        o.x = tf32r(acc[i].x * inv); o.y = tf32r(acc[i].y * inv);
        o.z = tf32r(acc[i].z * inv); o.w = tf32r(acc[i].w * inv);
        orow[i] = o;
    }
}

// ---------------------------------------------------------------------------
// Fused residual-add + LayerNorm (optionally tf32-rounds its output).
// ---------------------------------------------------------------------------
__device__ __forceinline__ float warpsum(float v) {
#pragma unroll
    for (int o = 16; o; o >>= 1) v += __shfl_xor_sync(0xffffffffu, v, o);
    return v;
}

template <int RND>
__global__ void __launch_bounds__(256)
ln_kernel(const float* __restrict__ x, const float* __restrict__ res,
          const float* __restrict__ g, const float* __restrict__ bta,
          float* __restrict__ out)
{
    const int row = blockIdx.x;
    const int t   = threadIdx.x;
    const float4* xr = (const float4*)(x   + (size_t)row * DMODEL);
    const float4* rr = (const float4*)(res + (size_t)row * DMODEL);

    float4 v = xr[t], r4 = rr[t];
    v.x += r4.x; v.y += r4.y; v.z += r4.z; v.w += r4.w;
    float s  = v.x + v.y + v.z + v.w;
    float ss = v.x * v.x + v.y * v.y + v.z * v.z + v.w * v.w;

    s  = warpsum(s);
    ss = warpsum(ss);

    __shared__ float aS[8], aQ[8];
    __shared__ float mu_s, rs_s;
    const int w = t >> 5, ln = t & 31;
    if (ln == 0) { aS[w] = s; aQ[w] = ss; }
    __syncthreads();
    if (t == 0) {
        float S = 0.f, Q2 = 0.f;
#pragma unroll
        for (int i = 0; i < 8; i++) { S += aS[i]; Q2 += aQ[i]; }
        float mu  = S * (1.f / DMODEL);
        float var = Q2 * (1.f / DMODEL) - mu * mu;
        mu_s = mu;
        rs_s = rsqrtf(var + 1e-6f);
    }
    __syncthreads();
    const float mu = mu_s, rs = rs_s;

    float4 gg = ((const float4*)g)[t];
    float4 bb = ((const float4*)bta)[t];
    float4 o;
    o.x = (v.x - mu) * rs * gg.x + bb.x;
    o.y = (v.y - mu) * rs * gg.y + bb.y;
    o.z = (v.z - mu) * rs * gg.z + bb.z;
    o.w = (v.w - mu) * rs * gg.w + bb.w;
    if (RND) { o.x = tf32r(o.x); o.y = tf32r(o.y); o.z = tf32r(o.z); o.w = tf32r(o.w); }
    ((float4*)(out + (size_t)row * DMODEL))[t] = o;
}

// ---------------------------------------------------------------------------
// Launch sequence
// ---------------------------------------------------------------------------
extern "C" void kernel_launch(void* const* d_in, const int* in_sizes, int n_in,
                              void* d_out, int out_size)
{
    const float* q_in  = (const float*)d_in[0];
    const float* k_in  = (const float*)d_in[1];
    const float* v_in  = (const float*)d_in[2];
    const float* wq    = (const float*)d_in[3];
    const float* bq    = (const float*)d_in[4];
    const float* wk    = (const float*)d_in[5];
    const float* bk    = (const float*)d_in[6];
    const float* wv    = (const float*)d_in[7];
    const float* bv    = (const float*)d_in[8];
    const float* wfc   = (const float*)d_in[9];
    const float* bfc   = (const float*)d_in[10];
    const float* w1    = (const float*)d_in[11];
    const float* b1    = (const float*)d_in[12];
    const float* w2    = (const float*)d_in[13];
    const float* b2    = (const float*)d_in[14];
    const float* ln_g  = (const float*)d_in[15];
    const float* ln_b  = (const float*)d_in[16];
    const float* rel_k = (const float*)d_in[17];
    const float* rel_v = (const float*)d_in[18];
    float* out = (float*)d_out;

    float *pQ, *pK, *pV, *pAtt, *pFc, *pLn1, *pH1, *pH2;
    float *prq, *prk, *prv, *prwq, *prwk, *prwv, *prwf, *prw1, *prw2;
    cudaGetSymbolAddress((void**)&pQ,   g_Q);
    cudaGetSymbolAddress((void**)&pK,   g_K);
    cudaGetSymbolAddress((void**)&pV,   g_V);
    cudaGetSymbolAddress((void**)&pAtt, g_att);
    cudaGetSymbolAddress((void**)&pFc,  g_fc);
    cudaGetSymbolAddress((void**)&pLn1, g_ln1);
    cudaGetSymbolAddress((void**)&pH1,  g_h1);
    cudaGetSymbolAddress((void**)&pH2,  g_h2);
    cudaGetSymbolAddress((void**)&prq,  g_rq);
    cudaGetSymbolAddress((void**)&prk,  g_rk);
    cudaGetSymbolAddress((void**)&prv,  g_rv);
    cudaGetSymbolAddress((void**)&prwq, g_rwq);
    cudaGetSymbolAddress((void**)&prwk, g_rwk);
    cudaGetSymbolAddress((void**)&prwv, g_rwv);
    cudaGetSymbolAddress((void**)&prwf, g_rwf);
    cudaGetSymbolAddress((void**)&prw1, g_rw1);
    cudaGetSymbolAddress((void**)&prw2, g_rw2);

    cudaFuncSetAttribute(attn_kernel,
                         cudaFuncAttributeMaxDynamicSharedMemorySize,
                         ATTN_SMEM_BYTES);
    cudaFuncSetAttribute(qkv_mm_kernel,
                         cudaFuncAttributeMaxDynamicSharedMemorySize, GSMEM_BYTES);
    cudaFuncSetAttribute(mm_kernel<0, 0>,
                         cudaFuncAttributeMaxDynamicSharedMemorySize, GSMEM_BYTES);
    cudaFuncSetAttribute(mm_kernel<1, 1>,
                         cudaFuncAttributeMaxDynamicSharedMemorySize, GSMEM_BYTES);

    // --- tf32 rna pre-rounding of external GEMM operands ---
    const int NA = MTOT * DMODEL / 4;       // activations (q,k,v)
    const int NW = DMODEL * DMODEL / 4;     // square weights
    const int NB = DMODEL * DINNER / 4;     // FFN weights
    round_kernel<<<(NA + 255) / 256, 256>>>(q_in, prq, NA);
    round_kernel<<<(NA + 255) / 256, 256>>>(k_in, prk, NA);
    round_kernel<<<(NA + 255) / 256, 256>>>(v_in, prv, NA);
    round_kernel<<<(NW + 255) / 256, 256>>>(wq,  prwq, NW);
    round_kernel<<<(NW + 255) / 256, 256>>>(wk,  prwk, NW);
    round_kernel<<<(NW + 255) / 256, 256>>>(wv,  prwv, NW);
    round_kernel<<<(NW + 255) / 256, 256>>>(wfc, prwf, NW);
    round_kernel<<<(NB + 255) / 256, 256>>>(w1,  prw1, NB);
    round_kernel<<<(NB + 255) / 256, 256>>>(w2,  prw2, NB);

    dim3 blk(256);
    dim3 g_qkv (DMODEL / BN, MTOT / BM, 3);
    dim3 g_1024(DMODEL / BN, MTOT / BM);
    dim3 g_4096(DINNER / BN, MTOT / BM);

    // Q/K/V projections (tensor cores)
    qkv_mm_kernel<<<g_qkv, blk, GSMEM_BYTES>>>(prq, prk, prv, prwq, prwk, prwv,
                                               bq, bk, bv, pQ, pK, pV);

    // fused relative attention (fp32; output rna-rounded)
    dim3 agrid(LSEQ / 128, NHEAD, BATCH);
    attn_kernel<<<agrid, 128, ATTN_SMEM_BYTES>>>(pQ, pK, pV, rel_k, rel_v, pAtt);

    // output projection + residual + LN (ln1 output rounded: feeds w1 GEMM)
    mm_kernel<0, 0><<<g_1024, blk, GSMEM_BYTES>>>(pAtt, prwf, bfc, pFc, DMODEL, DMODEL);
    ln_kernel<1><<<MTOT, 256>>>(pFc, q_in, ln_g, ln_b, pLn1);

    // FFN (h1 relu'd + rounded: feeds w2 GEMM) + residual + LN
    mm_kernel<1, 1><<<g_4096, blk, GSMEM_BYTES>>>(pLn1, prw1, b1, pH1, DINNER, DMODEL);
    mm_kernel<0, 0><<<g_1024, blk, GSMEM_BYTES>>>(pH1, prw2, b2, pH2, DMODEL, DINNER);
    ln_kernel<0><<<MTOT, 256>>>(pH2, pLn1, ln_g, ln_b, out);
}

// round 16
// speedup vs baseline: 2.6156x; 1.2612x over previous
#include <cuda_runtime.h>
#include <cuda_fp16.h>
#include <cstdint>

// ---------------------------------------------------------------------------
// Problem constants
// ---------------------------------------------------------------------------
#define BATCH   8
#define LSEQ    1024
#define DMODEL  1024
#define DINNER  4096
#define NHEAD   16
#define DK      64
#define MTOT    (BATCH * LSEQ)     // 8192 rows
#define MAXREL  16
#define NREL    (2 * MAXREL + 1)   // 33

// ---------------------------------------------------------------------------
// Scratch (static device globals; no allocation allowed)
// ---------------------------------------------------------------------------
__device__ float  g_Q   [(size_t)MTOT * DMODEL];
__device__ float  g_K   [(size_t)MTOT * DMODEL];
__device__ float  g_V   [(size_t)MTOT * DMODEL];
__device__ float  g_fc  [(size_t)MTOT * DMODEL];
__device__ float  g_ln1 [(size_t)MTOT * DMODEL];
__device__ float  g_h2  [(size_t)MTOT * DMODEL];
// fp16 activations (GEMM A operands)
__device__ __half g_hq  [(size_t)MTOT * DMODEL];
__device__ __half g_hk  [(size_t)MTOT * DMODEL];
__device__ __half g_hv  [(size_t)MTOT * DMODEL];
__device__ __half g_att16[(size_t)MTOT * DMODEL];
__device__ __half g_ln116[(size_t)MTOT * DMODEL];
__device__ __half g_h1h [(size_t)MTOT * DINNER];
// fp16 transposed weights [N][K]
__device__ __half g_twq [(size_t)DMODEL * DMODEL];
__device__ __half g_twk [(size_t)DMODEL * DMODEL];
__device__ __half g_twv [(size_t)DMODEL * DMODEL];
__device__ __half g_twf [(size_t)DMODEL * DMODEL];
__device__ __half g_tw1 [(size_t)DINNER * DMODEL];   // [4096][1024]
__device__ __half g_tw2 [(size_t)DMODEL * DINNER];   // [1024][4096]

// ---------------------------------------------------------------------------
// Helpers
// ---------------------------------------------------------------------------
__device__ __forceinline__ void cp_async_cg(uint32_t saddr, const void* g) {
    asm volatile("cp.async.cg.shared.global [%0], [%1], 16;"
                 :: "r"(saddr), "l"(g));
}
__device__ __forceinline__ void cp_commit() {
    asm volatile("cp.async.commit_group;" ::: "memory");
}
__device__ __forceinline__ void cp_wait1() {
    asm volatile("cp.async.wait_group 1;" ::: "memory");
}
__device__ __forceinline__ void cp_wait0() {
    asm volatile("cp.async.wait_group 0;" ::: "memory");
}

__device__ __forceinline__ void ldsm_x4(uint32_t r[4], uint32_t saddr) {
    asm volatile("ldmatrix.sync.aligned.m8n8.x4.shared.b16 {%0,%1,%2,%3}, [%4];"
                 : "=r"(r[0]), "=r"(r[1]), "=r"(r[2]), "=r"(r[3])
                 : "r"(saddr) : "memory");
}

__device__ __forceinline__ void mma_f16(float c[4], const uint32_t a[4],
                                        uint32_t b0, uint32_t b1) {
    asm volatile(
        "mma.sync.aligned.m16n8k16.row.col.f32.f16.f16.f32 "
        "{%0,%1,%2,%3},{%4,%5,%6,%7},{%8,%9},{%0,%1,%2,%3};"
        : "+f"(c[0]), "+f"(c[1]), "+f"(c[2]), "+f"(c[3])
        : "r"(a[0]), "r"(a[1]), "r"(a[2]), "r"(a[3]), "r"(b0), "r"(b1));
}

// ---------------------------------------------------------------------------
// fp16 tensor-core GEMM: C[M,N] = A[M,K] @ Wt[N,K]^T + bias (opt ReLU),
// C written fp32 or fp16 per OUTH. 128x128x32 tile, 256 thr (8 warps 2x4),
// warp tile 64x32, cp.async double buffer, ldmatrix A frags.
// Smem rows padded to 40 halves (80 B) -> conflict-free ldsm + B loads.
// ---------------------------------------------------------------------------
#define BM 128
#define BN 128
#define BK 32
#define APAD 40
#define ABUF_HALFS (BM * APAD)     // 5120 halves = 10240 B

template <int RELU, int OUTH>
__device__ __forceinline__ void mmh_tile(const __half* __restrict__ A,
                                         const __half* __restrict__ Wt,
                                         const float* __restrict__ bias,
                                         void* __restrict__ Cout,
                                         int N, int K, int bm, int bn)
{
    __shared__ __align__(16) __half As_s[2][ABUF_HALFS];
    __shared__ __align__(16) __half Bs_s[2][ABUF_HALFS];

    const int tid  = threadIdx.x;
    const int lane = tid & 31;
    const int warp = tid >> 5;
    const int wm = (warp >> 2) * 64;
    const int wn = (warp & 3) * 32;
    const int lr = lane >> 2;          // 0..7
    const int lc = lane & 3;           // 0..3

    const uint32_t a_base = (uint32_t)__cvta_generic_to_shared(As_s);
    const uint32_t b_base = (uint32_t)__cvta_generic_to_shared(Bs_s);

    // loader coords: 128 rows x 32 halves (4 chunks of 8 halves/16B)
    const int ld_r0 = tid >> 2;            // 0..63
    const int ld_c  = (tid & 3) * 8;       // halves

    // ldmatrix lane addressing (4 8x8-b16 matrices = m16k16 f16 A frag)
    const int lm_row = (lane & 7) + ((lane >> 3) & 1) * 8;
    const int lm_c   = (lane >> 4) * 8;    // halves

    float acc[4][4][4];
#pragma unroll
    for (int i = 0; i < 4; i++)
#pragma unroll
        for (int j = 0; j < 4; j++)
#pragma unroll
            for (int k = 0; k < 4; k++) acc[i][j][k] = 0.f;

#define LOAD_TILE_H(buf, k0)                                                   \
    {                                                                          \
        _Pragma("unroll")                                                      \
        for (int i = 0; i < 2; i++) {                                          \
            int r = ld_r0 + 64 * i;                                            \
            cp_async_cg(a_base + (uint32_t)(((buf) * ABUF_HALFS +              \
                         r * APAD + ld_c) * 2),                                \
                        A + (size_t)(bm + r) * K + (k0) + ld_c);               \
        }                                                                      \
        _Pragma("unroll")                                                      \
        for (int i = 0; i < 2; i++) {                                          \
            int r = ld_r0 + 64 * i;                                            \
            cp_async_cg(b_base + (uint32_t)(((buf) * ABUF_HALFS +              \
                         r * APAD + ld_c) * 2),                                \
                        Wt + (size_t)(bn + r) * K + (k0) + ld_c);              \
        }                                                                      \
        cp_commit();                                                           \
    }

    LOAD_TILE_H(0, 0);
    const int T = K / BK;
    for (int t = 0; t < T; t++) {
        if (t + 1 < T) { LOAD_TILE_H((t + 1) & 1, (t + 1) * BK); cp_wait1(); }
        else           { cp_wait0(); }
        __syncthreads();

        const uint32_t a_sb = a_base + (uint32_t)(((t & 1) * ABUF_HALFS) * 2);
        const __half*  Bb   = Bs_s[t & 1];

#pragma unroll
        for (int kk = 0; kk < BK; kk += 16) {
            uint32_t a[4][4];
#pragma unroll
            for (int mi = 0; mi < 4; mi++) {
                uint32_t addr = a_sb +
                    (uint32_t)(((wm + mi * 16 + lm_row) * APAD + kk + lm_c) * 2);
                ldsm_x4(a[mi], addr);
            }
            uint32_t b[4][2];
#pragma unroll
            for (int ni = 0; ni < 4; ni++) {
                const uint32_t* p = (const uint32_t*)
                    (Bb + (wn + ni * 8 + lr) * APAD + kk + 2 * lc);
                b[ni][0] = p[0];
                b[ni][1] = p[4];          // +8 halves
            }
#pragma unroll
            for (int mi = 0; mi < 4; mi++)
#pragma unroll
                for (int ni = 0; ni < 4; ni++)
                    mma_f16(acc[mi][ni], a[mi], b[ni][0], b[ni][1]);
        }
        __syncthreads();
    }
#undef LOAD_TILE_H

    // epilogue
#pragma unroll
    for (int mi = 0; mi < 4; mi++) {
        const int row = bm + wm + mi * 16 + lr;
#pragma unroll
        for (int ni = 0; ni < 4; ni++) {
            const int col = bn + wn + ni * 8 + 2 * lc;
            const float b0 = bias[col], b1 = bias[col + 1];
            float v0 = acc[mi][ni][0] + b0;
            float v1 = acc[mi][ni][1] + b1;
            float v2 = acc[mi][ni][2] + b0;
            float v3 = acc[mi][ni][3] + b1;
            if (RELU) {
                v0 = fmaxf(v0, 0.f); v1 = fmaxf(v1, 0.f);
                v2 = fmaxf(v2, 0.f); v3 = fmaxf(v3, 0.f);
            }
            if (OUTH) {
                __half* Ch = (__half*)Cout;
                __half2 lo = __floats2half2_rn(v0, v1);
                __half2 hi = __floats2half2_rn(v2, v3);
                *(__half2*)(Ch + (size_t)row * N + col)       = lo;
                *(__half2*)(Ch + (size_t)(row + 8) * N + col) = hi;
            } else {
                float* Cf = (float*)Cout;
                *(float2*)(Cf + (size_t)row * N + col)       = make_float2(v0, v1);
                *(float2*)(Cf + (size_t)(row + 8) * N + col) = make_float2(v2, v3);
            }
        }
    }
}

template <int RELU, int OUTH>
__global__ void __launch_bounds__(256)
mmh_kernel(const __half* __restrict__ A, const __half* __restrict__ Wt,
           const float* __restrict__ bias, void* __restrict__ C,
           int N, int K)
{
    mmh_tile<RELU, OUTH>(A, Wt, bias, C, N, K, blockIdx.y * BM, blockIdx.x * BN);
}

// Fused Q/K/V projection (z selects GEMM); fp16 in, fp32 out.
__global__ void __launch_bounds__(256)
qkv_mmh_kernel(const __half* __restrict__ hq, const __half* __restrict__ hk,
               const __half* __restrict__ hv,
               const __half* __restrict__ twq, const __half* __restrict__ twk,
               const __half* __restrict__ twv,
               const float* __restrict__ bq, const float* __restrict__ bk,
               const float* __restrict__ bv,
               float* __restrict__ oq, float* __restrict__ ok,
               float* __restrict__ ov)
{
    const int z = blockIdx.z;
    const __half* A    = (z == 0) ? hq  : (z == 1) ? hk  : hv;
    const __half* Wt   = (z == 0) ? twq : (z == 1) ? twk : twv;
    const float*  bias = (z == 0) ? bq  : (z == 1) ? bk  : bv;
    float*        C    = (z == 0) ? oq  : (z == 1) ? ok  : ov;
    mmh_tile<0, 0>(A, Wt, bias, C, DMODEL, DMODEL, blockIdx.y * BM, blockIdx.x * BN);
}

// ---------------------------------------------------------------------------
// One-time conversions: f32 -> f16 elementwise; f32 [K][N] -> f16 [N][K].
// ---------------------------------------------------------------------------
__global__ void __launch_bounds__(256)
tohalf_kernel(const float* __restrict__ src, __half* __restrict__ dst, int n4)
{
    int i = blockIdx.x * 256 + threadIdx.x;
    if (i < n4) {
        float4 v = ((const float4*)src)[i];
        __half2 h0 = __floats2half2_rn(v.x, v.y);
        __half2 h1 = __floats2half2_rn(v.z, v.w);
        ((__half2*)dst)[2 * i]     = h0;
        ((__half2*)dst)[2 * i + 1] = h1;
    }
}

__global__ void __launch_bounds__(256)
transpose_h_kernel(const float* __restrict__ src, __half* __restrict__ dst,
                   int K, int N)   // src [K][N] -> dst [N][K]
{
    __shared__ float tile[32][33];
    const int n0 = blockIdx.x * 32, k0 = blockIdx.y * 32;
    const int tx = threadIdx.x & 31, ty = threadIdx.x >> 5;  // 32 x 8
#pragma unroll
    for (int i = 0; i < 32; i += 8)
        tile[ty + i][tx] = src[(size_t)(k0 + ty + i) * N + n0 + tx];
    __syncthreads();
#pragma unroll
    for (int i = 0; i < 32; i += 8)
        dst[(size_t)(n0 + ty + i) * K + k0 + tx] =
            __float2half_rn(tile[tx][ty + i]);
}

// ---------------------------------------------------------------------------
// Fused relative-position attention (flash style, fp32 in, fp16 out).
// ---------------------------------------------------------------------------
#define BKV 64
#define ATTN_SMEM_FLOATS (BKV*DK + BKV*DK + 128*NREL + 128*NREL + NREL*DK)
#define ATTN_SMEM_BYTES  (ATTN_SMEM_FLOATS * 4)

__global__ void __launch_bounds__(128)
attn_kernel(const float* __restrict__ Q,
            const float* __restrict__ K,
            const float* __restrict__ V,
            const float* __restrict__ rel_k,
            const float* __restrict__ rel_v,
            __half* __restrict__ O)
{
    extern __shared__ float sm[];
    float* Kt   = sm;                        // [BKV][64]
    float* Vt   = Kt + BKV * DK;             // [BKV][64]
    float* Qrel = Vt + BKV * DK;             // [128][33]
    float* Bkt  = Qrel + 128 * NREL;         // [128][33]
    float* RelV = Bkt + 128 * NREL;          // [33][64]

    const int tid = threadIdx.x;
    const int b   = blockIdx.z;
    const int h   = blockIdx.y;
    const int q   = blockIdx.x * 128 + tid;

    for (int i = tid; i < NREL * DK / 4; i += 128)
        ((float4*)RelV)[i] = ((const float4*)rel_v)[i];

    const float* Qrow = Q + ((size_t)b * LSEQ + q) * DMODEL + h * DK;
    float4 q4[16];
#pragma unroll
    for (int i = 0; i < 16; i++) q4[i] = ((const float4*)Qrow)[i];

#pragma unroll 1
    for (int r = 0; r < NREL; r++) {
        const float4* rk = (const float4*)(rel_k + r * DK);
        float s = 0.f;
#pragma unroll
        for (int i = 0; i < 16; i++) {
            float4 kv = __ldg(rk + i);
            s += q4[i].x * kv.x + q4[i].y * kv.y + q4[i].z * kv.z + q4[i].w * kv.w;
        }
        Qrel[tid * NREL + r] = s;
        Bkt[tid * NREL + r]  = 0.f;
    }

    float m = -1e30f, l = 0.f;
    float4 acc[16];
#pragma unroll
    for (int i = 0; i < 16; i++) acc[i] = make_float4(0.f, 0.f, 0.f, 0.f);

    const float* Kbase = K + (size_t)b * LSEQ * DMODEL + h * DK;
    const float* Vbase = V + (size_t)b * LSEQ * DMODEL + h * DK;

    for (int k0 = 0; k0 < LSEQ; k0 += BKV) {
        __syncthreads();
        for (int i = tid; i < BKV * 16; i += 128) {
            int r = i >> 4, c = i & 15;
            ((float4*)Kt)[i] = __ldg((const float4*)(Kbase + (size_t)(k0 + r) * DMODEL) + c);
            ((float4*)Vt)[i] = __ldg((const float4*)(Vbase + (size_t)(k0 + r) * DMODEL) + c);
        }
        __syncthreads();

#pragma unroll 1
        for (int kk = 0; kk < BKV; kk++) {
            const float4* kr = (const float4*)(Kt + kk * DK);
            float s = 0.f;
#pragma unroll
            for (int i = 0; i < 16; i++) {
                float4 kv = kr[i];
                s += q4[i].x * kv.x + q4[i].y * kv.y + q4[i].z * kv.z + q4[i].w * kv.w;
            }
            int d   = (k0 + kk) - q;
            int idx = min(max(d, -MAXREL), MAXREL) + MAXREL;
            s = 0.125f * (s + Qrel[tid * NREL + idx]);

            if (s > m) {
                float f = __expf(m - s);
                m = s;
                l *= f;
#pragma unroll
                for (int i = 0; i < 16; i++) {
                    acc[i].x *= f; acc[i].y *= f; acc[i].z *= f; acc[i].w *= f;
                }
#pragma unroll
                for (int r = 0; r < NREL; r++) Bkt[tid * NREL + r] *= f;
            }
            float e = __expf(s - m);
            l += e;
            Bkt[tid * NREL + idx] += e;

            const float4* vr = (const float4*)(Vt + kk * DK);
#pragma unroll
            for (int i = 0; i < 16; i++) {
                float4 vv = vr[i];
                acc[i].x += e * vv.x; acc[i].y += e * vv.y;
                acc[i].z += e * vv.z; acc[i].w += e * vv.w;
            }
        }
    }

#pragma unroll 1
    for (int r = 0; r < NREL; r++) {
        float p = Bkt[tid * NREL + r];
        const float4* rv = (const float4*)(RelV + r * DK);
#pragma unroll
        for (int i = 0; i < 16; i++) {
            float4 t = rv[i];
            acc[i].x += p * t.x; acc[i].y += p * t.y;
            acc[i].z += p * t.z; acc[i].w += p * t.w;
        }
    }
    float inv = 1.f / l;
    __half* orow = O + ((size_t)b * LSEQ + q) * DMODEL + h * DK;
#pragma unroll
    for (int i = 0; i < 16; i++) {
        __half2 h0 = __floats2half2_rn(acc[i].x * inv, acc[i].y * inv);
        __half2 h1 = __floats2half2_rn(acc[i].z * inv, acc[i].w * inv);
        *(__half2*)(orow + i * 4)     = h0;
        *(__half2*)(orow + i * 4 + 2) = h1;
    }
}

// ---------------------------------------------------------------------------
// Fused residual-add + LayerNorm; DUAL also writes an fp16 copy.
// ---------------------------------------------------------------------------
__device__ __forceinline__ float warpsum(float v) {
#pragma unroll
    for (int o = 16; o; o >>= 1) v += __shfl_xor_sync(0xffffffffu, v, o);
    return v;
}

template <int DUAL>
__global__ void __launch_bounds__(256)
ln_kernel(const float* __restrict__ x, const float* __restrict__ res,
          const float* __restrict__ g, const float* __restrict__ bta,
          float* __restrict__ out, __half* __restrict__ outh)
{
    const int row = blockIdx.x;
    const int t   = threadIdx.x;
    const float4* xr = (const float4*)(x   + (size_t)row * DMODEL);
    const float4* rr = (const float4*)(res + (size_t)row * DMODEL);

    float4 v = xr[t], r4 = rr[t];
    v.x += r4.x; v.y += r4.y; v.z += r4.z; v.w += r4.w;
    float s  = v.x + v.y + v.z + v.w;
    float ss = v.x * v.x + v.y * v.y + v.z * v.z + v.w * v.w;

    s  = warpsum(s);
    ss = warpsum(ss);

    __shared__ float aS[8], aQ[8];
    __shared__ float mu_s, rs_s;
    const int w = t >> 5, ln = t & 31;
    if (ln == 0) { aS[w] = s; aQ[w] = ss; }
    __syncthreads();
    if (t == 0) {
        float S = 0.f, Q2 = 0.f;
#pragma unroll
        for (int i = 0; i < 8; i++) { S += aS[i]; Q2 += aQ[i]; }
        float mu  = S * (1.f / DMODEL);
        float var = Q2 * (1.f / DMODEL) - mu * mu;
        mu_s = mu;
        rs_s = rsqrtf(var + 1e-6f);
    }
    __syncthreads();
    const float mu = mu_s, rs = rs_s;

    float4 gg = ((const float4*)g)[t];
    float4 bb = ((const float4*)bta)[t];
    float4 o;
    o.x = (v.x - mu) * rs * gg.x + bb.x;
    o.y = (v.y - mu) * rs * gg.y + bb.y;
    o.z = (v.z - mu) * rs * gg.z + bb.z;
    o.w = (v.w - mu) * rs * gg.w + bb.w;
    ((float4*)(out + (size_t)row * DMODEL))[t] = o;
    if (DUAL) {
        __half2 h0 = __floats2half2_rn(o.x, o.y);
        __half2 h1 = __floats2half2_rn(o.z, o.w);
        __half* orow = outh + (size_t)row * DMODEL + t * 4;
        *(__half2*)(orow)     = h0;
        *(__half2*)(orow + 2) = h1;
    }
}

// ---------------------------------------------------------------------------
// Launch sequence
// ---------------------------------------------------------------------------
extern "C" void kernel_launch(void* const* d_in, const int* in_sizes, int n_in,
                              void* d_out, int out_size)
{
    const float* q_in  = (const float*)d_in[0];
    const float* k_in  = (const float*)d_in[1];
    const float* v_in  = (const float*)d_in[2];
    const float* wq    = (const float*)d_in[3];
    const float* bq    = (const float*)d_in[4];
    const float* wk    = (const float*)d_in[5];
    const float* bk    = (const float*)d_in[6];
    const float* wv    = (const float*)d_in[7];
    const float* bv    = (const float*)d_in[8];
    const float* wfc   = (const float*)d_in[9];
    const float* bfc   = (const float*)d_in[10];
    const float* w1    = (const float*)d_in[11];
    const float* b1    = (const float*)d_in[12];
    const float* w2    = (const float*)d_in[13];
    const float* b2    = (const float*)d_in[14];
    const float* ln_g  = (const float*)d_in[15];
    const float* ln_b  = (const float*)d_in[16];
    const float* rel_k = (const float*)d_in[17];
    const float* rel_v = (const float*)d_in[18];
    float* out = (float*)d_out;

    float  *pQ, *pK, *pV, *pFc, *pLn1, *pH2;
    __half *phq, *phk, *phv, *pAtt16, *pLn116, *pH1h;
    __half *ptwq, *ptwk, *ptwv, *ptwf, *ptw1, *ptw2;
    cudaGetSymbolAddress((void**)&pQ,     g_Q);
    cudaGetSymbolAddress((void**)&pK,     g_K);
    cudaGetSymbolAddress((void**)&pV,     g_V);
    cudaGetSymbolAddress((void**)&pFc,    g_fc);
    cudaGetSymbolAddress((void**)&pLn1,   g_ln1);
    cudaGetSymbolAddress((void**)&pH2,    g_h2);
    cudaGetSymbolAddress((void**)&phq,    g_hq);
    cudaGetSymbolAddress((void**)&phk,    g_hk);
    cudaGetSymbolAddress((void**)&phv,    g_hv);
    cudaGetSymbolAddress((void**)&pAtt16, g_att16);
    cudaGetSymbolAddress((void**)&pLn116, g_ln116);
    cudaGetSymbolAddress((void**)&pH1h,   g_h1h);
    cudaGetSymbolAddress((void**)&ptwq,   g_twq);
    cudaGetSymbolAddress((void**)&ptwk,   g_twk);
    cudaGetSymbolAddress((void**)&ptwv,   g_twv);
    cudaGetSymbolAddress((void**)&ptwf,   g_twf);
    cudaGetSymbolAddress((void**)&ptw1,   g_tw1);
    cudaGetSymbolAddress((void**)&ptw2,   g_tw2);

    cudaFuncSetAttribute(attn_kernel,
                         cudaFuncAttributeMaxDynamicSharedMemorySize,
                         ATTN_SMEM_BYTES);

    // --- one-time operand conversion: fp16 activations + transposed fp16 W ---
    const int NA = MTOT * DMODEL / 4;
    tohalf_kernel<<<(NA + 255) / 256, 256>>>(q_in, phq, NA);
    tohalf_kernel<<<(NA + 255) / 256, 256>>>(k_in, phk, NA);
    tohalf_kernel<<<(NA + 255) / 256, 256>>>(v_in, phv, NA);

    dim3 tgrid_sq(DMODEL / 32, DMODEL / 32);
    transpose_h_kernel<<<tgrid_sq, 256>>>(wq,  ptwq, DMODEL, DMODEL);
    transpose_h_kernel<<<tgrid_sq, 256>>>(wk,  ptwk, DMODEL, DMODEL);
    transpose_h_kernel<<<tgrid_sq, 256>>>(wv,  ptwv, DMODEL, DMODEL);
    transpose_h_kernel<<<tgrid_sq, 256>>>(wfc, ptwf, DMODEL, DMODEL);
    dim3 tgrid_w1(DINNER / 32, DMODEL / 32);   // src [1024][4096] -> dst [4096][1024]
    transpose_h_kernel<<<tgrid_w1, 256>>>(w1, ptw1, DMODEL, DINNER);
    dim3 tgrid_w2(DMODEL / 32, DINNER / 32);   // src [4096][1024] -> dst [1024][4096]
    transpose_h_kernel<<<tgrid_w2, 256>>>(w2, ptw2, DINNER, DMODEL);

    dim3 blk(256);
    dim3 g_qkv (DMODEL / BN, MTOT / BM, 3);
    dim3 g_1024(DMODEL / BN, MTOT / BM);
    dim3 g_4096(DINNER / BN, MTOT / BM);

    // Q/K/V projections (fp16 tensor cores, fp32 out)
    qkv_mmh_kernel<<<g_qkv, blk>>>(phq, phk, phv, ptwq, ptwk, ptwv,
                                   bq, bk, bv, pQ, pK, pV);

    // fused relative attention (fp32 compute, fp16 out)
    dim3 agrid(LSEQ / 128, NHEAD, BATCH);
    attn_kernel<<<agrid, 128, ATTN_SMEM_BYTES>>>(pQ, pK, pV, rel_k, rel_v, pAtt16);

    // output projection + residual + LN (dual: fp32 for residual + fp16 for w1)
    mmh_kernel<0, 0><<<g_1024, blk>>>(pAtt16, ptwf, bfc, pFc, DMODEL, DMODEL);
    ln_kernel<1><<<MTOT, 256>>>(pFc, q_in, ln_g, ln_b, pLn1, pLn116);

    // FFN + residual + LN
    mmh_kernel<1, 1><<<g_4096, blk>>>(pLn116, ptw1, b1, pH1h, DINNER, DMODEL);
    mmh_kernel<0, 0><<<g_1024, blk>>>(pH1h, ptw2, b2, pH2, DMODEL, DINNER);
    ln_kernel<0><<<MTOT, 256>>>(pH2, pLn1, ln_g, ln_b, out, ((__half*)0));
}